// round 1
// baseline (speedup 1.0000x reference)
#include <cuda_runtime.h>

// ---------------------------------------------------------------------------
// MultiHeadAttention: B=4, T=2048, C=1024, H=16, hs=64 (fp32)
//   qkv = x @ W_qkv^T + b_qkv            (8192 x 3072, K=1024)
//   att = softmax(q k^T / 8)             per (b,h)
//   attv = att @ v                       -> [B,T,C]
//   out = attv @ W_out^T + b_out         (8192 x 1024, K=1024)
// Round 1: fp32 SIMT baseline. 3 kernels, device-global scratch.
// ---------------------------------------------------------------------------

#define BATCH   4
#define T_SEQ   2048
#define NH      16
#define HS      64
#define CDIM    1024
#define MROWS   (BATCH * T_SEQ)          // 8192

// Scratch (device globals: allocation-free kernel_launch)
__device__ float g_q[BATCH * NH * T_SEQ * HS];      // [b,h,t,d]
__device__ float g_k[BATCH * NH * T_SEQ * HS];
__device__ float g_v[BATCH * NH * T_SEQ * HS];
__device__ float g_attv[BATCH * T_SEQ * CDIM];      // [b,t,h*hs+d]

// ---------------------------------------------------------------------------
// Generic SGEMM: C[m][n] = sum_k A[m][k] * B[n][k] + bias[n]
// Block tile 128x128, BK=16, 256 threads, 8x8 per-thread micro tile.
// EPI = 0: plain write to C
// EPI = 1: scatter QKV into g_q/g_k/g_v   (N = 3072)
// EPI = 2: A comes from g_attv, plain write to C
// ---------------------------------------------------------------------------
template <int EPI>
__global__ __launch_bounds__(256) void gemm_bias_kernel(
    const float* __restrict__ A, const float* __restrict__ B,
    const float* __restrict__ bias, float* __restrict__ C,
    int M, int N, int K)
{
    __shared__ float Ast[16][132];   // [k][m], pad 4 (keeps float4 alignment)
    __shared__ float Bst[16][132];   // [k][n]

    const float* Ap = (EPI == 2) ? g_attv : A;

    const int tid = threadIdx.x;
    const int txn = tid & 15;        // 0..15 (n direction)
    const int tym = tid >> 4;        // 0..15 (m direction)
    const int bm = blockIdx.y * 128;
    const int bn = blockIdx.x * 128;

    float acc[8][8];
#pragma unroll
    for (int i = 0; i < 8; ++i)
#pragma unroll
        for (int j = 0; j < 8; ++j) acc[i][j] = 0.0f;

    for (int kt = 0; kt < K; kt += 16) {
#pragma unroll
        for (int it = 0; it < 2; ++it) {
            int slot = tid + it * 256;          // 0..511
            int m = slot >> 2;                  // 0..127
            int k0 = (slot & 3) << 2;           // 0,4,8,12
            float4 av = *(const float4*)(Ap + (size_t)(bm + m) * K + kt + k0);
            Ast[k0 + 0][m] = av.x; Ast[k0 + 1][m] = av.y;
            Ast[k0 + 2][m] = av.z; Ast[k0 + 3][m] = av.w;
            float4 bv = *(const float4*)(B + (size_t)(bn + m) * K + kt + k0);
            Bst[k0 + 0][m] = bv.x; Bst[k0 + 1][m] = bv.y;
            Bst[k0 + 2][m] = bv.z; Bst[k0 + 3][m] = bv.w;
        }
        __syncthreads();

#pragma unroll
        for (int k = 0; k < 16; ++k) {
            float4 a0 = *(const float4*)&Ast[k][tym * 4];
            float4 a1 = *(const float4*)&Ast[k][64 + tym * 4];
            float4 b0 = *(const float4*)&Bst[k][txn * 4];
            float4 b1 = *(const float4*)&Bst[k][64 + txn * 4];
            float av[8] = {a0.x, a0.y, a0.z, a0.w, a1.x, a1.y, a1.z, a1.w};
            float bv[8] = {b0.x, b0.y, b0.z, b0.w, b1.x, b1.y, b1.z, b1.w};
#pragma unroll
            for (int i = 0; i < 8; ++i)
#pragma unroll
                for (int j = 0; j < 8; ++j)
                    acc[i][j] += av[i] * bv[j];
        }
        __syncthreads();
    }

    // Epilogue
#pragma unroll
    for (int i = 0; i < 8; ++i) {
        int m = bm + ((i < 4) ? (tym * 4 + i) : (64 + tym * 4 + (i - 4)));
#pragma unroll
        for (int j = 0; j < 8; ++j) {
            int n = bn + ((j < 4) ? (txn * 4 + j) : (64 + txn * 4 + (j - 4)));
            float val = acc[i][j] + bias[n];
            if (EPI == 1) {
                // qkv column mapping: reshape (B,T,H,3*hs)
                int b = m >> 11;            // m / 2048
                int t = m & 2047;
                int h = n / 192;            // 3*hs = 192
                int rr = n - h * 192;
                int sel = rr >> 6;          // 0:q 1:k 2:v
                int d = rr & 63;
                size_t dst = (((size_t)(b * NH + h) * T_SEQ) + t) * HS + d;
                if (sel == 0)      g_q[dst] = val;
                else if (sel == 1) g_k[dst] = val;
                else               g_v[dst] = val;
            } else {
                C[(size_t)m * N + n] = val;
            }
        }
    }
}

// ---------------------------------------------------------------------------
// Flash-style attention: one CTA handles 64 query rows for one (b,h).
// Online softmax over 32 key chunks of 64. 256 threads, 16x16 grid,
// each thread owns a 4x4 micro tile of S / O.
// ---------------------------------------------------------------------------
#define ATT_SMEM_FLOATS (4 * 64 * 68 + 3 * 64)
#define ATT_SMEM_BYTES  (ATT_SMEM_FLOATS * 4)

__global__ __launch_bounds__(256) void attn_kernel()
{
    extern __shared__ float sm[];
    float* Qt   = sm;                 // [d][r] 64x68 (q, pre-scaled by 1/8)
    float* Kt   = Qt + 64 * 68;       // [d][c] 64x68
    float* Vs   = Kt + 64 * 68;       // [c][d] 64x68
    float* Ps   = Vs + 64 * 68;       // [r][c] 64x68 (scores -> probs)
    float* m_s  = Ps + 64 * 68;       // [64] running max
    float* l_s  = m_s + 64;           // [64] running sum
    float* al_s = l_s + 64;           // [64] rescale factor

    const int bh = blockIdx.y;                 // 0..63  (b*16 + h)
    const int qb = blockIdx.x;                 // 0..31  (64-row q block)
    const float* qp = g_q + (size_t)bh * T_SEQ * HS + (size_t)qb * 64 * HS;
    const float* kp = g_k + (size_t)bh * T_SEQ * HS;
    const float* vp = g_v + (size_t)bh * T_SEQ * HS;

    const int tid = threadIdx.x;
    const int tx = tid & 15;       // col group
    const int ty = tid >> 4;       // row group

    // Load Q tile transposed, pre-scaled by 1/sqrt(64)
#pragma unroll
    for (int it = 0; it < 4; ++it) {
        int slot = tid + it * 256;        // 0..1023
        int r = slot >> 4;                // 0..63
        int d0 = (slot & 15) << 2;        // 0..60
        float4 qv = *(const float4*)(qp + r * HS + d0);
        Qt[(d0 + 0) * 68 + r] = qv.x * 0.125f;
        Qt[(d0 + 1) * 68 + r] = qv.y * 0.125f;
        Qt[(d0 + 2) * 68 + r] = qv.z * 0.125f;
        Qt[(d0 + 3) * 68 + r] = qv.w * 0.125f;
    }
    if (tid < 64) { m_s[tid] = -1e30f; l_s[tid] = 0.0f; }

    float acc[4][4];
#pragma unroll
    for (int i = 0; i < 4; ++i)
#pragma unroll
        for (int j = 0; j < 4; ++j) acc[i][j] = 0.0f;

    __syncthreads();

    for (int jc = 0; jc < T_SEQ / 64; ++jc) {
        const float* kj = kp + (size_t)jc * 64 * HS;
        const float* vj = vp + (size_t)jc * 64 * HS;
#pragma unroll
        for (int it = 0; it < 4; ++it) {
            int slot = tid + it * 256;
            int c = slot >> 4;
            int d0 = (slot & 15) << 2;
            float4 kv = *(const float4*)(kj + c * HS + d0);
            Kt[(d0 + 0) * 68 + c] = kv.x;
            Kt[(d0 + 1) * 68 + c] = kv.y;
            Kt[(d0 + 2) * 68 + c] = kv.z;
            Kt[(d0 + 3) * 68 + c] = kv.w;
            float4 vv = *(const float4*)(vj + c * HS + d0);
            *(float4*)&Vs[c * 68 + d0] = vv;
        }
        __syncthreads();

        // S = Q K^T (4x4 micro per thread)
        float s[4][4];
#pragma unroll
        for (int i = 0; i < 4; ++i)
#pragma unroll
            for (int j = 0; j < 4; ++j) s[i][j] = 0.0f;

#pragma unroll 8
        for (int d = 0; d < 64; ++d) {
            float4 a = *(const float4*)&Qt[d * 68 + ty * 4];
            float4 b = *(const float4*)&Kt[d * 68 + tx * 4];
            float av[4] = {a.x, a.y, a.z, a.w};
            float bv[4] = {b.x, b.y, b.z, b.w};
#pragma unroll
            for (int i = 0; i < 4; ++i)
#pragma unroll
                for (int j = 0; j < 4; ++j)
                    s[i][j] += av[i] * bv[j];
        }
#pragma unroll
        for (int i = 0; i < 4; ++i)
#pragma unroll
            for (int j = 0; j < 4; ++j)
                Ps[(ty * 4 + i) * 68 + tx * 4 + j] = s[i][j];
        __syncthreads();

        // Online softmax, one thread per row
        if (tid < 64) {
            float* row = &Ps[tid * 68];
            float mold = m_s[tid];
            float mj = mold;
#pragma unroll 8
            for (int c = 0; c < 64; ++c) mj = fmaxf(mj, row[c]);
            float alpha = __expf(mold - mj);
            float sum = 0.0f;
#pragma unroll 8
            for (int c = 0; c < 64; ++c) {
                float p = __expf(row[c] - mj);
                row[c] = p;
                sum += p;
            }
            l_s[tid] = l_s[tid] * alpha + sum;
            m_s[tid] = mj;
            al_s[tid] = alpha;
        }
        __syncthreads();

        // Rescale O and accumulate P @ V
#pragma unroll
        for (int i = 0; i < 4; ++i) {
            float a = al_s[ty * 4 + i];
#pragma unroll
            for (int j = 0; j < 4; ++j) acc[i][j] *= a;
        }
#pragma unroll 4
        for (int c = 0; c < 64; ++c) {
            float4 b = *(const float4*)&Vs[c * 68 + tx * 4];
#pragma unroll
            for (int i = 0; i < 4; ++i) {
                float p = Ps[(ty * 4 + i) * 68 + c];
                acc[i][0] += p * b.x;
                acc[i][1] += p * b.y;
                acc[i][2] += p * b.z;
                acc[i][3] += p * b.w;
            }
        }
        __syncthreads();
    }

    // Normalize and write to g_attv [b, t, h*64+d]
    const int b = bh >> 4;
    const int h = bh & 15;
#pragma unroll
    for (int i = 0; i < 4; ++i) {
        int r = ty * 4 + i;
        float inv = 1.0f / l_s[r];
        float4 o;
        o.x = acc[i][0] * inv;
        o.y = acc[i][1] * inv;
        o.z = acc[i][2] * inv;
        o.w = acc[i][3] * inv;
        size_t dst = ((size_t)(b * T_SEQ + qb * 64 + r)) * CDIM + h * HS + tx * 4;
        *(float4*)&g_attv[dst] = o;
    }
}

// ---------------------------------------------------------------------------
// Launch: 3 kernels, graph-capturable, no allocation/sync.
// ---------------------------------------------------------------------------
extern "C" void kernel_launch(void* const* d_in, const int* in_sizes, int n_in,
                              void* d_out, int out_size)
{
    const float* x    = (const float*)d_in[0];
    const float* Wqkv = (const float*)d_in[1];
    const float* bqkv = (const float*)d_in[2];
    const float* Wout = (const float*)d_in[3];
    const float* bout = (const float*)d_in[4];
    float* out = (float*)d_out;

    // QKV projection: M=8192, N=3072, K=1024 -> scatter to g_q/g_k/g_v
    gemm_bias_kernel<1><<<dim3(3072 / 128, MROWS / 128), 256>>>(
        x, Wqkv, bqkv, nullptr, MROWS, 3 * CDIM, CDIM);

    // Attention: grid (T/64, B*H)
    cudaFuncSetAttribute(attn_kernel,
                         cudaFuncAttributeMaxDynamicSharedMemorySize,
                         ATT_SMEM_BYTES);
    attn_kernel<<<dim3(T_SEQ / 64, BATCH * NH), 256, ATT_SMEM_BYTES>>>();

    // Output projection: M=8192, N=1024, K=1024, A = g_attv
    gemm_bias_kernel<2><<<dim3(CDIM / 128, MROWS / 128), 256>>>(
        nullptr, Wout, bout, out, MROWS, CDIM, CDIM);
}

// round 2
// speedup vs baseline: 2.3641x; 2.3641x over previous
#include <cuda_runtime.h>
#include <cstdint>

// ---------------------------------------------------------------------------
// MultiHeadAttention: B=4, T=2048, C=1024, H=16, hs=64 (fp32 I/O)
// Round 2: all matmuls on tensor cores via mma.sync m16n8k8 tf32,
//          softmax via FMA-pipe exp2 polynomial (no MUFU).
// ---------------------------------------------------------------------------

#define BATCH   4
#define T_SEQ   2048
#define NH      16
#define HS      64
#define CDIM    1024
#define MROWS   (BATCH * T_SEQ)          // 8192

// Scratch (device globals: allocation-free kernel_launch)
__device__ float g_q[BATCH * NH * T_SEQ * HS];      // [b,h,t,d]
__device__ float g_k[BATCH * NH * T_SEQ * HS];
__device__ float g_v[BATCH * NH * T_SEQ * HS];
__device__ float g_attv[BATCH * T_SEQ * CDIM];      // [b,t,h*hs+d]

// ---------------------------------------------------------------------------
// Helpers
// ---------------------------------------------------------------------------
__device__ __forceinline__ unsigned f2tf32(float x) {
    unsigned r;
    asm("cvt.rna.tf32.f32 %0, %1;" : "=r"(r) : "f"(x));
    return r;
}

__device__ __forceinline__ void mma_tf32(float4& d, const unsigned a[4],
                                         unsigned b0, unsigned b1) {
    asm volatile(
        "mma.sync.aligned.m16n8k8.row.col.f32.tf32.tf32.f32 "
        "{%0,%1,%2,%3}, {%4,%5,%6,%7}, {%8,%9}, {%0,%1,%2,%3};"
        : "+f"(d.x), "+f"(d.y), "+f"(d.z), "+f"(d.w)
        : "r"(a[0]), "r"(a[1]), "r"(a[2]), "r"(a[3]), "r"(b0), "r"(b1));
}

// exp2 on the FMA pipe: magic rounding + degree-4 Taylor, z <= 0 expected.
// Max rel err ~4e-5 on f in [-0.5, 0.5].
__device__ __forceinline__ float fast_exp2(float z) {
    z = fmaxf(z, -126.0f);
    float kf = z + 12582912.0f;              // 1.5 * 2^23 magic (round-to-int)
    int   ki = __float_as_int(kf);           // low bits hold round(z)
    float f  = z - (kf - 12582912.0f);       // f in [-0.5, 0.5]
    float p  = 0.0096181291f;
    p = fmaf(p, f, 0.0555041087f);
    p = fmaf(p, f, 0.2402265070f);
    p = fmaf(p, f, 0.6931471806f);
    p = fmaf(p, f, 1.0f);
    return __int_as_float(__float_as_int(p) + (ki << 23));
}

// ---------------------------------------------------------------------------
// Tensor-core SGEMM (tf32): C[m][n] = sum_k A[m][k]*B[n][k] + bias[n]
// Tile 128x128, BK=32, 256 threads = 8 warps (2m x 4n), warp tile 64x32.
// Double-buffered smem, register prefetch of globals.
// EPI = 1: scatter QKV into g_q/g_k/g_v   (N = 3072)
// EPI = 2: A comes from g_attv, plain write to C
// ---------------------------------------------------------------------------
#define GS          (128 * 36)              // floats per matrix per stage
#define GEMM_SMEM_BYTES (4 * GS * 4)        // 2 stages * (A + B)

template <int EPI>
__global__ __launch_bounds__(256) void gemm_tc(
    const float* __restrict__ A, const float* __restrict__ B,
    const float* __restrict__ bias, float* __restrict__ C,
    int M, int N, int K)
{
    extern __shared__ float smg[];
    float* Asm = smg;            // [2][128][36]
    float* Bsm = smg + 2 * GS;   // [2][128][36]

    const float* Ap = (EPI == 2) ? g_attv : A;

    const int tid  = threadIdx.x;
    const int lane = tid & 31;
    const int wid  = tid >> 5;
    const int lr   = lane >> 2;
    const int lc   = lane & 3;
    const int wm   = (wid >> 2) * 64;     // warp m offset (0 or 64)
    const int wn   = (wid & 3) * 32;      // warp n offset
    const int bm   = blockIdx.y * 128;
    const int bn   = blockIdx.x * 128;

    float4 acc[4][4];
#pragma unroll
    for (int i = 0; i < 4; ++i)
#pragma unroll
        for (int j = 0; j < 4; ++j) acc[i][j] = make_float4(0.f, 0.f, 0.f, 0.f);

    float4 aReg[4], bReg[4];
    const int NKT = K / 32;

    // load stage 0
#pragma unroll
    for (int it = 0; it < 4; ++it) {
        int slot = tid + it * 256;
        int row = slot >> 3;
        int k4 = (slot & 7) * 4;
        aReg[it] = *(const float4*)(Ap + (size_t)(bm + row) * K + k4);
        bReg[it] = *(const float4*)(B  + (size_t)(bn + row) * K + k4);
    }
#pragma unroll
    for (int it = 0; it < 4; ++it) {
        int slot = tid + it * 256;
        int row = slot >> 3;
        int k4 = (slot & 7) * 4;
        uint4 ua = {f2tf32(aReg[it].x), f2tf32(aReg[it].y), f2tf32(aReg[it].z), f2tf32(aReg[it].w)};
        *(uint4*)(Asm + row * 36 + k4) = ua;
        uint4 ub = {f2tf32(bReg[it].x), f2tf32(bReg[it].y), f2tf32(bReg[it].z), f2tf32(bReg[it].w)};
        *(uint4*)(Bsm + row * 36 + k4) = ub;
    }
    __syncthreads();

    for (int kt = 0; kt < NKT; ++kt) {
        const int cur = kt & 1;
        const int nxt = cur ^ 1;

        if (kt + 1 < NKT) {
            int kb = (kt + 1) * 32;
#pragma unroll
            for (int it = 0; it < 4; ++it) {
                int slot = tid + it * 256;
                int row = slot >> 3;
                int k4 = (slot & 7) * 4;
                aReg[it] = *(const float4*)(Ap + (size_t)(bm + row) * K + kb + k4);
                bReg[it] = *(const float4*)(B  + (size_t)(bn + row) * K + kb + k4);
            }
        }

        const unsigned* As = (const unsigned*)(Asm + cur * GS);
        const unsigned* Bs = (const unsigned*)(Bsm + cur * GS);
#pragma unroll
        for (int kk = 0; kk < 4; ++kk) {
            int k0 = kk * 8;
            unsigned af[4][4];
            unsigned bf[4][2];
#pragma unroll
            for (int i = 0; i < 4; ++i) {
                int m0 = wm + i * 16 + lr;
                af[i][0] = As[(m0)     * 36 + k0 + lc];
                af[i][1] = As[(m0 + 8) * 36 + k0 + lc];
                af[i][2] = As[(m0)     * 36 + k0 + lc + 4];
                af[i][3] = As[(m0 + 8) * 36 + k0 + lc + 4];
            }
#pragma unroll
            for (int j = 0; j < 4; ++j) {
                int n0 = wn + j * 8 + lr;
                bf[j][0] = Bs[n0 * 36 + k0 + lc];
                bf[j][1] = Bs[n0 * 36 + k0 + lc + 4];
            }
#pragma unroll
            for (int i = 0; i < 4; ++i)
#pragma unroll
                for (int j = 0; j < 4; ++j)
                    mma_tf32(acc[i][j], af[i], bf[j][0], bf[j][1]);
        }

        if (kt + 1 < NKT) {
            float* Asw = Asm + nxt * GS;
            float* Bsw = Bsm + nxt * GS;
#pragma unroll
            for (int it = 0; it < 4; ++it) {
                int slot = tid + it * 256;
                int row = slot >> 3;
                int k4 = (slot & 7) * 4;
                uint4 ua = {f2tf32(aReg[it].x), f2tf32(aReg[it].y), f2tf32(aReg[it].z), f2tf32(aReg[it].w)};
                *(uint4*)(Asw + row * 36 + k4) = ua;
                uint4 ub = {f2tf32(bReg[it].x), f2tf32(bReg[it].y), f2tf32(bReg[it].z), f2tf32(bReg[it].w)};
                *(uint4*)(Bsw + row * 36 + k4) = ub;
            }
        }
        __syncthreads();
    }

    // Epilogue
#pragma unroll
    for (int i = 0; i < 4; ++i) {
        int m0 = bm + wm + i * 16 + lr;     // rows m0 and m0+8
#pragma unroll
        for (int j = 0; j < 4; ++j) {
            int n0 = bn + wn + j * 8 + lc * 2;   // cols n0, n0+1
            float bia0 = bias[n0], bia1 = bias[n0 + 1];
            float v00 = acc[i][j].x + bia0;
            float v01 = acc[i][j].y + bia1;
            float v10 = acc[i][j].z + bia0;
            float v11 = acc[i][j].w + bia1;
            if (EPI == 1) {
#pragma unroll
                for (int e = 0; e < 4; ++e) {
                    int m = m0 + ((e >> 1) ? 8 : 0);
                    int n = n0 + (e & 1);
                    float val = (e == 0) ? v00 : (e == 1) ? v01 : (e == 2) ? v10 : v11;
                    int b = m >> 11;
                    int t = m & 2047;
                    int h = n / 192;
                    int rr = n - h * 192;
                    int sel = rr >> 6;
                    int d = rr & 63;
                    size_t dst = (((size_t)(b * NH + h) * T_SEQ) + t) * HS + d;
                    if (sel == 0)      g_q[dst] = val;
                    else if (sel == 1) g_k[dst] = val;
                    else               g_v[dst] = val;
                }
            } else {
                float2 r0 = {v00, v01};
                float2 r1 = {v10, v11};
                *(float2*)(C + (size_t)m0 * N + n0) = r0;
                *(float2*)(C + (size_t)(m0 + 8) * N + n0) = r1;
            }
        }
    }
}

// ---------------------------------------------------------------------------
// Flash attention with mma.sync tf32.
// CTA: 128 q rows for one (b,h); 8 warps, warp owns 16 rows.
// Online softmax over 32 key chunks of 64, exp2 domain (Q pre-scaled by
// 0.125*log2(e)).  P bounces through smem to re-fragment for PV.
// ---------------------------------------------------------------------------
#define SP 68     // Ps stride (conflict-free for A-frag pattern)
#define SK 72     // Kt/Vs stride (conflict-free for B-frag pattern)
#define ATT_SMEM_BYTES ((128 * SP + 2 * 64 * SK) * 4)

__global__ __launch_bounds__(256) void attn_tc_kernel()
{
    extern __shared__ float sm[];
    float* Ps = sm;                    // [128][68] (Q staging, then P)
    float* Kt = sm + 128 * SP;         // [64][72]  K transposed [d][c]
    float* Vs = Kt + 64 * SK;          // [64][72]  V [c][d]

    const int bh = blockIdx.y;
    const int qb = blockIdx.x;
    const float* qp = g_q + ((size_t)bh * T_SEQ + (size_t)qb * 128) * HS;
    const float* kp = g_k + (size_t)bh * T_SEQ * HS;
    const float* vp = g_v + (size_t)bh * T_SEQ * HS;

    const int tid  = threadIdx.x;
    const int lane = tid & 31;
    const int wid  = tid >> 5;
    const int lr   = lane >> 2;
    const int lc   = lane & 3;
    const int w16  = wid * 16;

    // Stage Q, pre-scaled so scores are already in log2 units
    const float qs = 0.125f * 1.4426950408889634f;
#pragma unroll
    for (int it = 0; it < 8; ++it) {
        int slot = tid + it * 256;       // 0..2047
        int r = slot >> 4;
        int d0 = (slot & 15) * 4;
        float4 v = *(const float4*)(qp + r * HS + d0);
        v.x *= qs; v.y *= qs; v.z *= qs; v.w *= qs;
        *(float4*)(Ps + r * SP + d0) = v;
    }
    __syncthreads();

    unsigned qf[8][4];
#pragma unroll
    for (int kk = 0; kk < 8; ++kk) {
        int k0 = kk * 8;
        qf[kk][0] = f2tf32(Ps[(w16 + lr)     * SP + k0 + lc]);
        qf[kk][1] = f2tf32(Ps[(w16 + lr + 8) * SP + k0 + lc]);
        qf[kk][2] = f2tf32(Ps[(w16 + lr)     * SP + k0 + lc + 4]);
        qf[kk][3] = f2tf32(Ps[(w16 + lr + 8) * SP + k0 + lc + 4]);
    }
    __syncthreads();

    float4 o[8];
#pragma unroll
    for (int j = 0; j < 8; ++j) o[j] = make_float4(0.f, 0.f, 0.f, 0.f);
    float m0 = -1e30f, m1 = -1e30f, l0 = 0.f, l1 = 0.f;

    unsigned* pp = (unsigned*)Ps;
    unsigned* kt = (unsigned*)Kt;
    unsigned* vs = (unsigned*)Vs;

    for (int jc = 0; jc < T_SEQ / 64; ++jc) {
        const float* kj = kp + (size_t)jc * 64 * HS;
        const float* vj = vp + (size_t)jc * 64 * HS;
#pragma unroll
        for (int it = 0; it < 4; ++it) {
            int slot = tid + it * 256;     // 0..1023
            int c = slot >> 4;             // key index 0..63
            int d0 = (slot & 15) * 4;
            float4 kv = *(const float4*)(kj + c * HS + d0);
            kt[(d0 + 0) * SK + c] = f2tf32(kv.x);
            kt[(d0 + 1) * SK + c] = f2tf32(kv.y);
            kt[(d0 + 2) * SK + c] = f2tf32(kv.z);
            kt[(d0 + 3) * SK + c] = f2tf32(kv.w);
            float4 vv = *(const float4*)(vj + c * HS + d0);
            uint4 uv = {f2tf32(vv.x), f2tf32(vv.y), f2tf32(vv.z), f2tf32(vv.w)};
            *(uint4*)(vs + c * SK + d0) = uv;
        }
        __syncthreads();

        // S = Q K^T   (per-warp 16x64)
        float4 s[8];
#pragma unroll
        for (int j = 0; j < 8; ++j) s[j] = make_float4(0.f, 0.f, 0.f, 0.f);
#pragma unroll
        for (int kk = 0; kk < 8; ++kk) {
            int k0 = kk * 8;
#pragma unroll
            for (int j = 0; j < 8; ++j) {
                unsigned b0 = kt[(k0 + lc)     * SK + j * 8 + lr];
                unsigned b1 = kt[(k0 + lc + 4) * SK + j * 8 + lr];
                mma_tf32(s[j], qf[kk], b0, b1);
            }
        }

        // Online softmax (exp2 domain)
        float mx0 = -1e30f, mx1 = -1e30f;
#pragma unroll
        for (int j = 0; j < 8; ++j) {
            mx0 = fmaxf(mx0, fmaxf(s[j].x, s[j].y));
            mx1 = fmaxf(mx1, fmaxf(s[j].z, s[j].w));
        }
        mx0 = fmaxf(mx0, __shfl_xor_sync(0xffffffffu, mx0, 1));
        mx0 = fmaxf(mx0, __shfl_xor_sync(0xffffffffu, mx0, 2));
        mx1 = fmaxf(mx1, __shfl_xor_sync(0xffffffffu, mx1, 1));
        mx1 = fmaxf(mx1, __shfl_xor_sync(0xffffffffu, mx1, 2));
        float mn0 = fmaxf(m0, mx0);
        float mn1 = fmaxf(m1, mx1);
        float a0 = fast_exp2(m0 - mn0);
        float a1 = fast_exp2(m1 - mn1);
        m0 = mn0; m1 = mn1;

        float s0 = 0.f, s1 = 0.f;
        int row0 = (w16 + lr) * SP;
        int row1 = (w16 + lr + 8) * SP;
#pragma unroll
        for (int j = 0; j < 8; ++j) {
            float px = fast_exp2(s[j].x - mn0);
            float py = fast_exp2(s[j].y - mn0);
            float pz = fast_exp2(s[j].z - mn1);
            float pw = fast_exp2(s[j].w - mn1);
            s0 += px + py;
            s1 += pz + pw;
            int cix = j * 8 + lc * 2;
            pp[row0 + cix]     = f2tf32(px);
            pp[row0 + cix + 1] = f2tf32(py);
            pp[row1 + cix]     = f2tf32(pz);
            pp[row1 + cix + 1] = f2tf32(pw);
        }
        s0 += __shfl_xor_sync(0xffffffffu, s0, 1);
        s0 += __shfl_xor_sync(0xffffffffu, s0, 2);
        s1 += __shfl_xor_sync(0xffffffffu, s1, 1);
        s1 += __shfl_xor_sync(0xffffffffu, s1, 2);
        l0 = l0 * a0 + s0;
        l1 = l1 * a1 + s1;
#pragma unroll
        for (int j = 0; j < 8; ++j) {
            o[j].x *= a0; o[j].y *= a0;
            o[j].z *= a1; o[j].w *= a1;
        }
        __syncthreads();

        // O += P V
#pragma unroll
        for (int kk = 0; kk < 8; ++kk) {
            int k0 = kk * 8;
            unsigned af[4];
            af[0] = pp[(w16 + lr)     * SP + k0 + lc];
            af[1] = pp[(w16 + lr + 8) * SP + k0 + lc];
            af[2] = pp[(w16 + lr)     * SP + k0 + lc + 4];
            af[3] = pp[(w16 + lr + 8) * SP + k0 + lc + 4];
#pragma unroll
            for (int j = 0; j < 8; ++j) {
                unsigned b0 = vs[(k0 + lc)     * SK + j * 8 + lr];
                unsigned b1 = vs[(k0 + lc + 4) * SK + j * 8 + lr];
                mma_tf32(o[j], af, b0, b1);
            }
        }
        __syncthreads();
    }

    // Epilogue: normalize and write [b, t, h*64+d]
    float inv0 = 1.0f / l0;
    float inv1 = 1.0f / l1;
    const int b = bh >> 4;
    const int h = bh & 15;
    const int t0 = qb * 128 + w16 + lr;
#pragma unroll
    for (int j = 0; j < 8; ++j) {
        int col = h * 64 + j * 8 + lc * 2;
        float2 r0 = {o[j].x * inv0, o[j].y * inv0};
        float2 r1 = {o[j].z * inv1, o[j].w * inv1};
        *(float2*)(g_attv + (size_t)(b * T_SEQ + t0) * CDIM + col) = r0;
        *(float2*)(g_attv + (size_t)(b * T_SEQ + t0 + 8) * CDIM + col) = r1;
    }
}

// ---------------------------------------------------------------------------
// Launch: 3 kernels, graph-capturable, no allocation/sync.
// ---------------------------------------------------------------------------
extern "C" void kernel_launch(void* const* d_in, const int* in_sizes, int n_in,
                              void* d_out, int out_size)
{
    const float* x    = (const float*)d_in[0];
    const float* Wqkv = (const float*)d_in[1];
    const float* bqkv = (const float*)d_in[2];
    const float* Wout = (const float*)d_in[3];
    const float* bout = (const float*)d_in[4];
    float* out = (float*)d_out;

    cudaFuncSetAttribute(gemm_tc<1>, cudaFuncAttributeMaxDynamicSharedMemorySize, GEMM_SMEM_BYTES);
    cudaFuncSetAttribute(gemm_tc<2>, cudaFuncAttributeMaxDynamicSharedMemorySize, GEMM_SMEM_BYTES);
    cudaFuncSetAttribute(attn_tc_kernel, cudaFuncAttributeMaxDynamicSharedMemorySize, ATT_SMEM_BYTES);

    // QKV projection: M=8192, N=3072, K=1024 -> scatter to g_q/g_k/g_v
    gemm_tc<1><<<dim3(3072 / 128, MROWS / 128), 256, GEMM_SMEM_BYTES>>>(
        x, Wqkv, bqkv, nullptr, MROWS, 3 * CDIM, CDIM);

    // Attention: grid (T/128, B*H)
    attn_tc_kernel<<<dim3(T_SEQ / 128, BATCH * NH), 256, ATT_SMEM_BYTES>>>();

    // Output projection: M=8192, N=1024, K=1024, A = g_attv
    gemm_tc<2><<<dim3(CDIM / 128, MROWS / 128), 256, GEMM_SMEM_BYTES>>>(
        nullptr, Wout, bout, out, MROWS, CDIM, CDIM);
}

// round 3
// speedup vs baseline: 3.2000x; 1.3536x over previous
#include <cuda_runtime.h>
#include <cstdint>

// ---------------------------------------------------------------------------
// MultiHeadAttention: B=4, T=2048, C=1024, H=16, hs=64 (fp32 I/O)
// Round 3: ldmatrix (LDSM) fragment feeds for all mma.sync tf32 paths.
// ---------------------------------------------------------------------------

#define BATCH   4
#define T_SEQ   2048
#define NH      16
#define HS      64
#define CDIM    1024
#define MROWS   (BATCH * T_SEQ)          // 8192

__device__ float g_q[BATCH * NH * T_SEQ * HS];      // [b,h,t,d]
__device__ float g_k[BATCH * NH * T_SEQ * HS];
__device__ float g_v[BATCH * NH * T_SEQ * HS];
__device__ float g_attv[BATCH * T_SEQ * CDIM];      // [b,t,h*hs+d]

// ---------------------------------------------------------------------------
// Helpers
// ---------------------------------------------------------------------------
__device__ __forceinline__ unsigned f2tf32(float x) {
    unsigned r;
    asm("cvt.rna.tf32.f32 %0, %1;" : "=r"(r) : "f"(x));
    return r;
}

__device__ __forceinline__ void mma_tf32(float4& d, const unsigned a[4],
                                         unsigned b0, unsigned b1) {
    asm volatile(
        "mma.sync.aligned.m16n8k8.row.col.f32.tf32.tf32.f32 "
        "{%0,%1,%2,%3}, {%4,%5,%6,%7}, {%8,%9}, {%0,%1,%2,%3};"
        : "+f"(d.x), "+f"(d.y), "+f"(d.z), "+f"(d.w)
        : "r"(a[0]), "r"(a[1]), "r"(a[2]), "r"(a[3]), "r"(b0), "r"(b1));
}

// ldmatrix.x4 on tf32 data: each m8n8.b16 tile == 8x4 tile of 32-bit elems,
// thread t holds [t/4][t%4] — the exact m16n8k8 tf32 fragment mapping.
__device__ __forceinline__ void ldsm4(unsigned& r0, unsigned& r1,
                                      unsigned& r2, unsigned& r3,
                                      unsigned addr) {
    asm volatile(
        "ldmatrix.sync.aligned.m8n8.x4.shared.b16 {%0,%1,%2,%3}, [%4];"
        : "=r"(r0), "=r"(r1), "=r"(r2), "=r"(r3) : "r"(addr));
}

// exp2 on the FMA pipe (no MUFU): magic rounding + degree-4 poly.
__device__ __forceinline__ float fast_exp2(float z) {
    z = fmaxf(z, -126.0f);
    float kf = z + 12582912.0f;
    int   ki = __float_as_int(kf);
    float f  = z - (kf - 12582912.0f);
    float p  = 0.0096181291f;
    p = fmaf(p, f, 0.0555041087f);
    p = fmaf(p, f, 0.2402265070f);
    p = fmaf(p, f, 0.6931471806f);
    p = fmaf(p, f, 1.0f);
    return __int_as_float(__float_as_int(p) + (ki << 23));
}

// ---------------------------------------------------------------------------
// Tensor-core GEMM (tf32): C[m][n] = sum_k A[m][k]*B[n][k] + bias[n]
// 128x128 tile, BK=32, 8 warps (2m x 4n), warp tile 64x32, double buffered.
// Fragments fed by ldmatrix.x4. Stride 36 floats => LDSM conflict-free.
// ---------------------------------------------------------------------------
#define GS          (128 * 36)
#define GEMM_SMEM_BYTES (4 * GS * 4)

template <int EPI>
__global__ __launch_bounds__(256, 2) void gemm_tc(
    const float* __restrict__ A, const float* __restrict__ B,
    const float* __restrict__ bias, float* __restrict__ C,
    int M, int N, int K)
{
    extern __shared__ float smg[];
    float* Asm = smg;            // [2][128][36]
    float* Bsm = smg + 2 * GS;   // [2][128][36]

    const float* Ap = (EPI == 2) ? g_attv : A;

    const int tid  = threadIdx.x;
    const int lane = tid & 31;
    const int wid  = tid >> 5;
    const int lr   = lane >> 2;
    const int lc   = lane & 3;
    const int wm   = (wid >> 2) * 64;
    const int wn   = (wid & 3) * 32;
    const int bm   = blockIdx.y * 128;
    const int bn   = blockIdx.x * 128;

    // LDSM per-lane base addresses (bytes)
    // A map: g0 (r,k0) g1 (r+8,k0) g2 (r,k0+4) g3 (r+8,k0+4)
    const int rA = wm + (lane & 7) + ((lane >> 3) & 1) * 8;
    const int cA = ((lane >> 4) & 1) * 4;
    // B map: g0 (r,k0) g1 (r,k0+4) g2 (r+8,k0) g3 (r+8,k0+4)
    const int rB = wn + (lane & 7) + ((lane >> 4) & 1) * 8;
    const int cB = ((lane >> 3) & 1) * 4;
    const unsigned aBase = (unsigned)__cvta_generic_to_shared(Asm) + (rA * 36 + cA) * 4;
    const unsigned bBase = (unsigned)__cvta_generic_to_shared(Bsm) + (rB * 36 + cB) * 4;

    float4 acc[4][4];
#pragma unroll
    for (int i = 0; i < 4; ++i)
#pragma unroll
        for (int j = 0; j < 4; ++j) acc[i][j] = make_float4(0.f, 0.f, 0.f, 0.f);

    float4 aReg[4], bReg[4];
    const int NKT = K / 32;

#pragma unroll
    for (int it = 0; it < 4; ++it) {
        int slot = tid + it * 256;
        int row = slot >> 3;
        int k4 = (slot & 7) * 4;
        aReg[it] = *(const float4*)(Ap + (size_t)(bm + row) * K + k4);
        bReg[it] = *(const float4*)(B  + (size_t)(bn + row) * K + k4);
    }
#pragma unroll
    for (int it = 0; it < 4; ++it) {
        int slot = tid + it * 256;
        int row = slot >> 3;
        int k4 = (slot & 7) * 4;
        uint4 ua = {f2tf32(aReg[it].x), f2tf32(aReg[it].y), f2tf32(aReg[it].z), f2tf32(aReg[it].w)};
        *(uint4*)(Asm + row * 36 + k4) = ua;
        uint4 ub = {f2tf32(bReg[it].x), f2tf32(bReg[it].y), f2tf32(bReg[it].z), f2tf32(bReg[it].w)};
        *(uint4*)(Bsm + row * 36 + k4) = ub;
    }
    __syncthreads();

    for (int kt = 0; kt < NKT; ++kt) {
        const int cur = kt & 1;
        const int nxt = cur ^ 1;
        const unsigned stOff = cur * (GS * 4);

        if (kt + 1 < NKT) {
            int kb = (kt + 1) * 32;
#pragma unroll
            for (int it = 0; it < 4; ++it) {
                int slot = tid + it * 256;
                int row = slot >> 3;
                int k4 = (slot & 7) * 4;
                aReg[it] = *(const float4*)(Ap + (size_t)(bm + row) * K + kb + k4);
                bReg[it] = *(const float4*)(B  + (size_t)(bn + row) * K + kb + k4);
            }
        }

#pragma unroll
        for (int kk = 0; kk < 4; ++kk) {
            const unsigned kOff = stOff + kk * 8 * 4;
            unsigned af[4][4];
            unsigned bf[4][2];
#pragma unroll
            for (int i = 0; i < 4; ++i)
                ldsm4(af[i][0], af[i][1], af[i][2], af[i][3],
                      aBase + kOff + i * (16 * 36 * 4));
            ldsm4(bf[0][0], bf[0][1], bf[1][0], bf[1][1], bBase + kOff);
            ldsm4(bf[2][0], bf[2][1], bf[3][0], bf[3][1],
                  bBase + kOff + 16 * 36 * 4);
#pragma unroll
            for (int i = 0; i < 4; ++i)
#pragma unroll
                for (int j = 0; j < 4; ++j)
                    mma_tf32(acc[i][j], af[i], bf[j][0], bf[j][1]);
        }

        if (kt + 1 < NKT) {
            float* Asw = Asm + nxt * GS;
            float* Bsw = Bsm + nxt * GS;
#pragma unroll
            for (int it = 0; it < 4; ++it) {
                int slot = tid + it * 256;
                int row = slot >> 3;
                int k4 = (slot & 7) * 4;
                uint4 ua = {f2tf32(aReg[it].x), f2tf32(aReg[it].y), f2tf32(aReg[it].z), f2tf32(aReg[it].w)};
                *(uint4*)(Asw + row * 36 + k4) = ua;
                uint4 ub = {f2tf32(bReg[it].x), f2tf32(bReg[it].y), f2tf32(bReg[it].z), f2tf32(bReg[it].w)};
                *(uint4*)(Bsw + row * 36 + k4) = ub;
            }
        }
        __syncthreads();
    }

    // Epilogue
#pragma unroll
    for (int i = 0; i < 4; ++i) {
        int m0 = bm + wm + i * 16 + lr;
#pragma unroll
        for (int j = 0; j < 4; ++j) {
            int n0 = bn + wn + j * 8 + lc * 2;
            float bia0 = bias[n0], bia1 = bias[n0 + 1];
            float v00 = acc[i][j].x + bia0;
            float v01 = acc[i][j].y + bia1;
            float v10 = acc[i][j].z + bia0;
            float v11 = acc[i][j].w + bia1;
            if (EPI == 1) {
#pragma unroll
                for (int e = 0; e < 4; ++e) {
                    int m = m0 + ((e >> 1) ? 8 : 0);
                    int n = n0 + (e & 1);
                    float val = (e == 0) ? v00 : (e == 1) ? v01 : (e == 2) ? v10 : v11;
                    int b = m >> 11;
                    int t = m & 2047;
                    int h = n / 192;
                    int rr = n - h * 192;
                    int sel = rr >> 6;
                    int d = rr & 63;
                    size_t dst = (((size_t)(b * NH + h) * T_SEQ) + t) * HS + d;
                    if (sel == 0)      g_q[dst] = val;
                    else if (sel == 1) g_k[dst] = val;
                    else               g_v[dst] = val;
                }
            } else {
                float2 r0 = {v00, v01};
                float2 r1 = {v10, v11};
                *(float2*)(C + (size_t)m0 * N + n0) = r0;
                *(float2*)(C + (size_t)(m0 + 8) * N + n0) = r1;
            }
        }
    }
}

// ---------------------------------------------------------------------------
// Flash attention, mma.sync tf32 + LDSM feeds.
// CTA: 128 q rows of one (b,h); 8 warps x 16 rows. 32 key chunks of 64.
// K stored natural [c][d] (B-frag rows = keys); V transposed [d][c];
// P rows are warp-private in smem (no sync needed around P).
// ---------------------------------------------------------------------------
#define PS 68
#define ATT_SMEM_BYTES ((128 * PS + 2 * 64 * PS) * 4)

__global__ __launch_bounds__(256, 2) void attn_tc_kernel()
{
    extern __shared__ float sm[];
    float* Ps = sm;                    // [128][68]  Q staging, then P
    float* Ks = sm + 128 * PS;         // [64][68]   K natural [c][d]
    float* Vt = Ks + 64 * PS;          // [64][68]   V transposed [d][c]

    const int bh = blockIdx.y;
    const int qb = blockIdx.x;
    const float* qp = g_q + ((size_t)bh * T_SEQ + (size_t)qb * 128) * HS;
    const float* kp = g_k + (size_t)bh * T_SEQ * HS;
    const float* vp = g_v + (size_t)bh * T_SEQ * HS;

    const int tid  = threadIdx.x;
    const int lane = tid & 31;
    const int wid  = tid >> 5;
    const int lr   = lane >> 2;
    const int lc   = lane & 3;
    const int w16  = wid * 16;

    // LDSM lane maps
    const int rA = (lane & 7) + ((lane >> 3) & 1) * 8;   // A-frag row offset
    const int cA = ((lane >> 4) & 1) * 4;
    const int rB = (lane & 7) + ((lane >> 4) & 1) * 8;   // B-frag row offset
    const int cB = ((lane >> 3) & 1) * 4;

    const unsigned psU = (unsigned)__cvta_generic_to_shared(Ps);
    const unsigned pQ = psU + ((w16 + rA) * PS + cA) * 4;             // A frags (Q, P)
    const unsigned pK = (unsigned)__cvta_generic_to_shared(Ks) + (rB * PS + cB) * 4;
    const unsigned pV = (unsigned)__cvta_generic_to_shared(Vt) + (rB * PS + cB) * 4;

    // Stage Q scaled into log2 units
    const float qs = 0.125f * 1.4426950408889634f;
#pragma unroll
    for (int it = 0; it < 8; ++it) {
        int slot = tid + it * 256;
        int r = slot >> 4;
        int d0 = (slot & 15) * 4;
        float4 v = *(const float4*)(qp + r * HS + d0);
        v.x *= qs; v.y *= qs; v.z *= qs; v.w *= qs;
        uint4 u = {f2tf32(v.x), f2tf32(v.y), f2tf32(v.z), f2tf32(v.w)};
        *(uint4*)(Ps + r * PS + d0) = u;
    }
    __syncthreads();

    unsigned qf[8][4];
#pragma unroll
    for (int kk = 0; kk < 8; ++kk)
        ldsm4(qf[kk][0], qf[kk][1], qf[kk][2], qf[kk][3], pQ + kk * 8 * 4);
    // Note: Ps will be reused for P; qf lives in registers.

    float4 o[8];
#pragma unroll
    for (int j = 0; j < 8; ++j) o[j] = make_float4(0.f, 0.f, 0.f, 0.f);
    float m0 = -1e30f, m1 = -1e30f, l0 = 0.f, l1 = 0.f;

    unsigned* pp = (unsigned*)Ps;

    for (int jc = 0; jc < T_SEQ / 64; ++jc) {
        const float* kj = kp + (size_t)jc * 64 * HS;
        const float* vj = vp + (size_t)jc * 64 * HS;

        // Load chunk into registers first (overlaps with barrier wait)
        float4 kReg[4], vReg[4];
#pragma unroll
        for (int it = 0; it < 4; ++it) {
            int slot = tid + it * 256;
            int c = slot >> 4;
            int d0 = (slot & 15) * 4;
            kReg[it] = *(const float4*)(kj + c * HS + d0);
            vReg[it] = *(const float4*)(vj + c * HS + d0);
        }
        __syncthreads();   // previous iteration done reading Ks/Vt
#pragma unroll
        for (int it = 0; it < 4; ++it) {
            int slot = tid + it * 256;
            int c = slot >> 4;
            int d0 = (slot & 15) * 4;
            uint4 uk = {f2tf32(kReg[it].x), f2tf32(kReg[it].y),
                        f2tf32(kReg[it].z), f2tf32(kReg[it].w)};
            *(uint4*)(Ks + c * PS + d0) = uk;
            ((unsigned*)Vt)[(d0 + 0) * PS + c] = f2tf32(vReg[it].x);
            ((unsigned*)Vt)[(d0 + 1) * PS + c] = f2tf32(vReg[it].y);
            ((unsigned*)Vt)[(d0 + 2) * PS + c] = f2tf32(vReg[it].z);
            ((unsigned*)Vt)[(d0 + 3) * PS + c] = f2tf32(vReg[it].w);
        }
        __syncthreads();

        // S = Q K^T (warp 16x64)
        float4 s[8];
#pragma unroll
        for (int j = 0; j < 8; ++j) s[j] = make_float4(0.f, 0.f, 0.f, 0.f);
#pragma unroll
        for (int kk = 0; kk < 8; ++kk) {
            const unsigned kOff = kk * 8 * 4;
            unsigned bf[8][2];
#pragma unroll
            for (int jp = 0; jp < 4; ++jp)
                ldsm4(bf[jp * 2][0], bf[jp * 2][1], bf[jp * 2 + 1][0], bf[jp * 2 + 1][1],
                      pK + kOff + jp * (16 * PS * 4));
#pragma unroll
            for (int j = 0; j < 8; ++j)
                mma_tf32(s[j], qf[kk], bf[j][0], bf[j][1]);
        }

        // Online softmax (exp2 domain)
        float mx0 = -1e30f, mx1 = -1e30f;
#pragma unroll
        for (int j = 0; j < 8; ++j) {
            mx0 = fmaxf(mx0, fmaxf(s[j].x, s[j].y));
            mx1 = fmaxf(mx1, fmaxf(s[j].z, s[j].w));
        }
        mx0 = fmaxf(mx0, __shfl_xor_sync(0xffffffffu, mx0, 1));
        mx0 = fmaxf(mx0, __shfl_xor_sync(0xffffffffu, mx0, 2));
        mx1 = fmaxf(mx1, __shfl_xor_sync(0xffffffffu, mx1, 1));
        mx1 = fmaxf(mx1, __shfl_xor_sync(0xffffffffu, mx1, 2));
        float mn0 = fmaxf(m0, mx0);
        float mn1 = fmaxf(m1, mx1);
        float a0 = fast_exp2(m0 - mn0);
        float a1 = fast_exp2(m1 - mn1);
        m0 = mn0; m1 = mn1;

        float s0 = 0.f, s1 = 0.f;
        const int row0 = (w16 + lr) * PS;
        const int row1 = (w16 + lr + 8) * PS;
#pragma unroll
        for (int j = 0; j < 8; ++j) {
            float px = fast_exp2(s[j].x - mn0);
            float py = fast_exp2(s[j].y - mn0);
            float pz = fast_exp2(s[j].z - mn1);
            float pw = fast_exp2(s[j].w - mn1);
            s0 += px + py;
            s1 += pz + pw;
            int cix = j * 8 + lc * 2;
            uint2 u0 = {f2tf32(px), f2tf32(py)};
            uint2 u1 = {f2tf32(pz), f2tf32(pw)};
            *(uint2*)&pp[row0 + cix] = u0;
            *(uint2*)&pp[row1 + cix] = u1;
        }
        s0 += __shfl_xor_sync(0xffffffffu, s0, 1);
        s0 += __shfl_xor_sync(0xffffffffu, s0, 2);
        s1 += __shfl_xor_sync(0xffffffffu, s1, 1);
        s1 += __shfl_xor_sync(0xffffffffu, s1, 2);
        l0 = l0 * a0 + s0;
        l1 = l1 * a1 + s1;
#pragma unroll
        for (int j = 0; j < 8; ++j) {
            o[j].x *= a0; o[j].y *= a0;
            o[j].z *= a1; o[j].w *= a1;
        }
        __syncwarp();   // P rows are warp-private; warp-level fence suffices

        // O += P V
#pragma unroll
        for (int kk = 0; kk < 8; ++kk) {
            const unsigned kOff = kk * 8 * 4;
            unsigned af[4];
            ldsm4(af[0], af[1], af[2], af[3], pQ + kOff);
            unsigned bf[8][2];
#pragma unroll
            for (int jp = 0; jp < 4; ++jp)
                ldsm4(bf[jp * 2][0], bf[jp * 2][1], bf[jp * 2 + 1][0], bf[jp * 2 + 1][1],
                      pV + kOff + jp * (16 * PS * 4));
#pragma unroll
            for (int j = 0; j < 8; ++j)
                mma_tf32(o[j], af, bf[j][0], bf[j][1]);
        }
    }

    // Epilogue
    float inv0 = 1.0f / l0;
    float inv1 = 1.0f / l1;
    const int b = bh >> 4;
    const int h = bh & 15;
    const int t0 = qb * 128 + w16 + lr;
#pragma unroll
    for (int j = 0; j < 8; ++j) {
        int col = h * 64 + j * 8 + lc * 2;
        float2 r0 = {o[j].x * inv0, o[j].y * inv0};
        float2 r1 = {o[j].z * inv1, o[j].w * inv1};
        *(float2*)(g_attv + (size_t)(b * T_SEQ + t0) * CDIM + col) = r0;
        *(float2*)(g_attv + (size_t)(b * T_SEQ + t0 + 8) * CDIM + col) = r1;
    }
}

// ---------------------------------------------------------------------------
extern "C" void kernel_launch(void* const* d_in, const int* in_sizes, int n_in,
                              void* d_out, int out_size)
{
    const float* x    = (const float*)d_in[0];
    const float* Wqkv = (const float*)d_in[1];
    const float* bqkv = (const float*)d_in[2];
    const float* Wout = (const float*)d_in[3];
    const float* bout = (const float*)d_in[4];
    float* out = (float*)d_out;

    cudaFuncSetAttribute(gemm_tc<1>, cudaFuncAttributeMaxDynamicSharedMemorySize, GEMM_SMEM_BYTES);
    cudaFuncSetAttribute(gemm_tc<2>, cudaFuncAttributeMaxDynamicSharedMemorySize, GEMM_SMEM_BYTES);
    cudaFuncSetAttribute(attn_tc_kernel, cudaFuncAttributeMaxDynamicSharedMemorySize, ATT_SMEM_BYTES);

    gemm_tc<1><<<dim3(3072 / 128, MROWS / 128), 256, GEMM_SMEM_BYTES>>>(
        x, Wqkv, bqkv, nullptr, MROWS, 3 * CDIM, CDIM);

    attn_tc_kernel<<<dim3(T_SEQ / 128, BATCH * NH), 256, ATT_SMEM_BYTES>>>();

    gemm_tc<2><<<dim3(CDIM / 128, MROWS / 128), 256, GEMM_SMEM_BYTES>>>(
        nullptr, Wout, bout, out, MROWS, CDIM, CDIM);
}

// round 4
// speedup vs baseline: 3.7752x; 1.1798x over previous
#include <cuda_runtime.h>
#include <cstdint>

// ---------------------------------------------------------------------------
// MultiHeadAttention: B=4, T=2048, C=1024, H=16, hs=64 (fp32 I/O)
// Round 4: pre-converted tf32 operands everywhere + cp.async double-buffered
// staging; attention PV uses conflict-free scalar-LDS B-fragments (no V
// transpose). All mma.sync m16n8k8 tf32.
// ---------------------------------------------------------------------------

#define BATCH   4
#define T_SEQ   2048
#define NH      16
#define HS      64
#define CDIM    1024
#define MROWS   (BATCH * T_SEQ)          // 8192

// Scratch (device globals). All hold tf32-bit-pattern floats.
__device__ float g_xa[MROWS * CDIM];                // x, tf32
__device__ float g_wqkv[3 * CDIM * CDIM];           // W_qkv, tf32
__device__ float g_wout[CDIM * CDIM];               // W_out, tf32
__device__ float g_q[BATCH * NH * T_SEQ * HS];      // [b,h,t,d], tf32, pre-scaled
__device__ float g_k[BATCH * NH * T_SEQ * HS];      // tf32
__device__ float g_v[BATCH * NH * T_SEQ * HS];      // tf32
__device__ float g_attv[BATCH * T_SEQ * CDIM];      // [b,t,h*hs+d], tf32

// ---------------------------------------------------------------------------
// Helpers
// ---------------------------------------------------------------------------
__device__ __forceinline__ unsigned f2tf32(float x) {
    unsigned r;
    asm("cvt.rna.tf32.f32 %0, %1;" : "=r"(r) : "f"(x));
    return r;
}

__device__ __forceinline__ void mma_tf32(float4& d, const unsigned a[4],
                                         unsigned b0, unsigned b1) {
    asm volatile(
        "mma.sync.aligned.m16n8k8.row.col.f32.tf32.tf32.f32 "
        "{%0,%1,%2,%3}, {%4,%5,%6,%7}, {%8,%9}, {%0,%1,%2,%3};"
        : "+f"(d.x), "+f"(d.y), "+f"(d.z), "+f"(d.w)
        : "r"(a[0]), "r"(a[1]), "r"(a[2]), "r"(a[3]), "r"(b0), "r"(b1));
}

__device__ __forceinline__ void ldsm4(unsigned& r0, unsigned& r1,
                                      unsigned& r2, unsigned& r3,
                                      unsigned addr) {
    asm volatile(
        "ldmatrix.sync.aligned.m8n8.x4.shared.b16 {%0,%1,%2,%3}, [%4];"
        : "=r"(r0), "=r"(r1), "=r"(r2), "=r"(r3) : "r"(addr));
}

__device__ __forceinline__ void cp16(unsigned dst, const void* src) {
    asm volatile("cp.async.cg.shared.global [%0], [%1], 16;"
                 :: "r"(dst), "l"(src));
}
#define CP_COMMIT() asm volatile("cp.async.commit_group;" ::: "memory")
#define CP_WAIT0()  asm volatile("cp.async.wait_group 0;" ::: "memory")

// exp2 on the FMA pipe (no MUFU): magic rounding + degree-4 poly.
__device__ __forceinline__ float fast_exp2(float z) {
    z = fmaxf(z, -126.0f);
    float kf = z + 12582912.0f;
    int   ki = __float_as_int(kf);
    float f  = z - (kf - 12582912.0f);
    float p  = 0.0096181291f;
    p = fmaf(p, f, 0.0555041087f);
    p = fmaf(p, f, 0.2402265070f);
    p = fmaf(p, f, 0.6931471806f);
    p = fmaf(p, f, 1.0f);
    return __int_as_float(__float_as_int(p) + (ki << 23));
}

// ---------------------------------------------------------------------------
// Elementwise fp32 -> tf32 convert (vectorized, grid-stride)
// ---------------------------------------------------------------------------
__global__ void cvt_tf32_kernel(const float4* __restrict__ s,
                                float4* __restrict__ d, int n4) {
    for (int i = blockIdx.x * blockDim.x + threadIdx.x; i < n4;
         i += gridDim.x * blockDim.x) {
        float4 v = s[i];
        uint4 u = {f2tf32(v.x), f2tf32(v.y), f2tf32(v.z), f2tf32(v.w)};
        ((uint4*)d)[i] = u;
    }
}

// ---------------------------------------------------------------------------
// Tensor-core GEMM (tf32, pre-converted operands):
//   C[m][n] = sum_k A[m][k]*B[n][k] + bias[n]
// 128x128 tile, BK=32, 8 warps (2m x 4n), cp.async double-buffered.
// EPI=1: A=g_xa, B=g_wqkv, scatter q/k/v (q scaled, all tf32)
// EPI=2: A=g_attv, B=g_wout, plain fp32 write to C
// ---------------------------------------------------------------------------
#define GS          (128 * 36)
#define GEMM_SMEM_BYTES (4 * GS * 4)

template <int EPI>
__global__ __launch_bounds__(256, 2) void gemm_tc(
    const float* __restrict__ bias, float* __restrict__ C, int N, int K)
{
    extern __shared__ float smg[];
    float* Asm = smg;            // [2][128][36]
    float* Bsm = smg + 2 * GS;

    const float* Ap = (EPI == 2) ? g_attv : g_xa;
    const float* Bp = (EPI == 2) ? g_wout : g_wqkv;

    const int tid  = threadIdx.x;
    const int lane = tid & 31;
    const int wid  = tid >> 5;
    const int lr   = lane >> 2;
    const int lc   = lane & 3;
    const int wm   = (wid >> 2) * 64;
    const int wn   = (wid & 3) * 32;
    const int bm   = blockIdx.y * 128;
    const int bn   = blockIdx.x * 128;

    // cp.async per-thread mapping: rows tid>>3 + 32*it, k chunk (tid&7)*4
    const int crow = tid >> 3;
    const int ck4  = (tid & 7) * 4;
    const float* aS = Ap + (size_t)(bm + crow) * K + ck4;
    const float* bS = Bp + (size_t)(bn + crow) * K + ck4;
    const unsigned aDst = (unsigned)__cvta_generic_to_shared(Asm) + (crow * 36 + ck4) * 4;
    const unsigned bDst = (unsigned)__cvta_generic_to_shared(Bsm) + (crow * 36 + ck4) * 4;

    // LDSM lane maps (same as R3)
    const int rA = wm + (lane & 7) + ((lane >> 3) & 1) * 8;
    const int cA = ((lane >> 4) & 1) * 4;
    const int rB = wn + (lane & 7) + ((lane >> 4) & 1) * 8;
    const int cB = ((lane >> 3) & 1) * 4;
    const unsigned aBase = (unsigned)__cvta_generic_to_shared(Asm) + (rA * 36 + cA) * 4;
    const unsigned bBase = (unsigned)__cvta_generic_to_shared(Bsm) + (rB * 36 + cB) * 4;

    float4 acc[4][4];
#pragma unroll
    for (int i = 0; i < 4; ++i)
#pragma unroll
        for (int j = 0; j < 4; ++j) acc[i][j] = make_float4(0.f, 0.f, 0.f, 0.f);

    const int NKT = K / 32;

    auto issue = [&](int kt, int buf) {
        const unsigned so = buf * (GS * 4);
        const int ko = kt * 32;
#pragma unroll
        for (int it = 0; it < 4; ++it) {
            cp16(aDst + so + it * (32 * 36 * 4), aS + ko + (size_t)it * 32 * K);
            cp16(bDst + so + it * (32 * 36 * 4), bS + ko + (size_t)it * 32 * K);
        }
    };

    issue(0, 0);
    CP_COMMIT();

    for (int kt = 0; kt < NKT; ++kt) {
        const int cur = kt & 1;
        CP_WAIT0();
        __syncthreads();
        if (kt + 1 < NKT) { issue(kt + 1, cur ^ 1); CP_COMMIT(); }

        const unsigned stOff = cur * (GS * 4);
#pragma unroll
        for (int kk = 0; kk < 4; ++kk) {
            const unsigned kOff = stOff + kk * 8 * 4;
            unsigned af[4][4];
            unsigned bf[4][2];
#pragma unroll
            for (int i = 0; i < 4; ++i)
                ldsm4(af[i][0], af[i][1], af[i][2], af[i][3],
                      aBase + kOff + i * (16 * 36 * 4));
            ldsm4(bf[0][0], bf[0][1], bf[1][0], bf[1][1], bBase + kOff);
            ldsm4(bf[2][0], bf[2][1], bf[3][0], bf[3][1],
                  bBase + kOff + 16 * 36 * 4);
#pragma unroll
            for (int i = 0; i < 4; ++i)
#pragma unroll
                for (int j = 0; j < 4; ++j)
                    mma_tf32(acc[i][j], af[i], bf[j][0], bf[j][1]);
        }
        // no trailing sync: next-iter top sync orders buffer reuse
    }

    // Epilogue
    const float QS = 0.125f * 1.4426950408889634f;
#pragma unroll
    for (int i = 0; i < 4; ++i) {
        int m0 = bm + wm + i * 16 + lr;
#pragma unroll
        for (int j = 0; j < 4; ++j) {
            int n0 = bn + wn + j * 8 + lc * 2;
            float bia0 = bias[n0], bia1 = bias[n0 + 1];
            float v00 = acc[i][j].x + bia0;
            float v01 = acc[i][j].y + bia1;
            float v10 = acc[i][j].z + bia0;
            float v11 = acc[i][j].w + bia1;
            if (EPI == 1) {
#pragma unroll
                for (int e = 0; e < 4; ++e) {
                    int m = m0 + ((e >> 1) ? 8 : 0);
                    int n = n0 + (e & 1);
                    float val = (e == 0) ? v00 : (e == 1) ? v01 : (e == 2) ? v10 : v11;
                    int b = m >> 11;
                    int t = m & 2047;
                    int h = n / 192;
                    int rr = n - h * 192;
                    int sel = rr >> 6;
                    int d = rr & 63;
                    size_t dst = (((size_t)(b * NH + h) * T_SEQ) + t) * HS + d;
                    if (sel == 0)      g_q[dst] = __uint_as_float(f2tf32(val * QS));
                    else if (sel == 1) g_k[dst] = __uint_as_float(f2tf32(val));
                    else               g_v[dst] = __uint_as_float(f2tf32(val));
                }
            } else {
                float2 r0 = {v00, v01};
                float2 r1 = {v10, v11};
                *(float2*)(C + (size_t)m0 * N + n0) = r0;
                *(float2*)(C + (size_t)(m0 + 8) * N + n0) = r1;
            }
        }
    }
}

// ---------------------------------------------------------------------------
// Flash attention, tf32 mma + LDSM + cp.async double-buffered K/V.
// CTA: 128 q rows of one (b,h); 8 warps x 16 rows; 32 key chunks of 64.
// K natural [c][d] stride 68 (LDSM B-frags); V natural [c][d] stride 72
// (scalar-LDS B-frags, banks 8*lc+lr all distinct => conflict-free).
// ---------------------------------------------------------------------------
#define PS 68
#define SV 72
#define ATT_SMEM_BYTES ((128 * PS + 2 * 64 * PS + 2 * 64 * SV) * 4)

__global__ __launch_bounds__(256, 2) void attn_tc_kernel()
{
    extern __shared__ float sm[];
    float* Ps = sm;                        // [128][68]  Q staging, then P
    float* Ks = sm + 128 * PS;             // [2][64][68]
    float* Vs = Ks + 2 * 64 * PS;          // [2][64][72]

    const int bh = blockIdx.y;
    const int qb = blockIdx.x;
    const float* qp = g_q + ((size_t)bh * T_SEQ + (size_t)qb * 128) * HS;
    const float* kp = g_k + (size_t)bh * T_SEQ * HS;
    const float* vp = g_v + (size_t)bh * T_SEQ * HS;

    const int tid  = threadIdx.x;
    const int lane = tid & 31;
    const int wid  = tid >> 5;
    const int lr   = lane >> 2;
    const int lc   = lane & 3;
    const int w16  = wid * 16;

    // cp.async mapping for K/V chunks
    const int cc  = tid >> 4;             // +16*it
    const int cd0 = (tid & 15) * 4;
    const unsigned ksB = (unsigned)__cvta_generic_to_shared(Ks);
    const unsigned vsB = (unsigned)__cvta_generic_to_shared(Vs);

    // LDSM lane maps
    const int rA = (lane & 7) + ((lane >> 3) & 1) * 8;
    const int cA = ((lane >> 4) & 1) * 4;
    const int rB = (lane & 7) + ((lane >> 4) & 1) * 8;
    const int cB = ((lane >> 3) & 1) * 4;

    const unsigned pQ = (unsigned)__cvta_generic_to_shared(Ps) + ((w16 + rA) * PS + cA) * 4;
    const unsigned pK = ksB + (rB * PS + cB) * 4;

    auto issueKV = [&](int jc, int buf) {
        const float* kj = kp + (size_t)jc * 64 * HS;
        const float* vj = vp + (size_t)jc * 64 * HS;
#pragma unroll
        for (int it = 0; it < 4; ++it) {
            int c = cc + it * 16;
            cp16(ksB + ((buf * 64 + c) * PS + cd0) * 4, kj + c * HS + cd0);
            cp16(vsB + ((buf * 64 + c) * SV + cd0) * 4, vj + c * HS + cd0);
        }
    };

    issueKV(0, 0);
    CP_COMMIT();

    // Stage Q (already tf32 + scaled)
#pragma unroll
    for (int it = 0; it < 8; ++it) {
        int slot = tid + it * 256;
        int r = slot >> 4;
        int d0 = (slot & 15) * 4;
        *(uint4*)(Ps + r * PS + d0) = *(const uint4*)(qp + r * HS + d0);
    }
    __syncthreads();

    unsigned qf[8][4];
#pragma unroll
    for (int kk = 0; kk < 8; ++kk)
        ldsm4(qf[kk][0], qf[kk][1], qf[kk][2], qf[kk][3], pQ + kk * 8 * 4);

    float4 o[8];
#pragma unroll
    for (int j = 0; j < 8; ++j) o[j] = make_float4(0.f, 0.f, 0.f, 0.f);
    float m0 = -1e30f, m1 = -1e30f, l0 = 0.f, l1 = 0.f;

    unsigned* pp = (unsigned*)Ps;

    for (int jc = 0; jc < T_SEQ / 64; ++jc) {
        const int cur = jc & 1;
        CP_WAIT0();
        __syncthreads();
        if (jc + 1 < T_SEQ / 64) { issueKV(jc + 1, cur ^ 1); CP_COMMIT(); }

        // S = Q K^T (warp 16x64)
        const unsigned pKc = pK + cur * (64 * PS * 4);
        float4 s[8];
#pragma unroll
        for (int j = 0; j < 8; ++j) s[j] = make_float4(0.f, 0.f, 0.f, 0.f);
#pragma unroll
        for (int kk = 0; kk < 8; ++kk) {
            const unsigned kOff = kk * 8 * 4;
            unsigned bf[8][2];
#pragma unroll
            for (int jp = 0; jp < 4; ++jp)
                ldsm4(bf[jp * 2][0], bf[jp * 2][1], bf[jp * 2 + 1][0], bf[jp * 2 + 1][1],
                      pKc + kOff + jp * (16 * PS * 4));
#pragma unroll
            for (int j = 0; j < 8; ++j)
                mma_tf32(s[j], qf[kk], bf[j][0], bf[j][1]);
        }

        // Online softmax (exp2 domain)
        float mx0 = -1e30f, mx1 = -1e30f;
#pragma unroll
        for (int j = 0; j < 8; ++j) {
            mx0 = fmaxf(mx0, fmaxf(s[j].x, s[j].y));
            mx1 = fmaxf(mx1, fmaxf(s[j].z, s[j].w));
        }
        mx0 = fmaxf(mx0, __shfl_xor_sync(0xffffffffu, mx0, 1));
        mx0 = fmaxf(mx0, __shfl_xor_sync(0xffffffffu, mx0, 2));
        mx1 = fmaxf(mx1, __shfl_xor_sync(0xffffffffu, mx1, 1));
        mx1 = fmaxf(mx1, __shfl_xor_sync(0xffffffffu, mx1, 2));
        float mn0 = fmaxf(m0, mx0);
        float mn1 = fmaxf(m1, mx1);
        float a0 = fast_exp2(m0 - mn0);
        float a1 = fast_exp2(m1 - mn1);
        m0 = mn0; m1 = mn1;

        float s0 = 0.f, s1 = 0.f;
        const int row0 = (w16 + lr) * PS;
        const int row1 = (w16 + lr + 8) * PS;
#pragma unroll
        for (int j = 0; j < 8; ++j) {
            float px = fast_exp2(s[j].x - mn0);
            float py = fast_exp2(s[j].y - mn0);
            float pz = fast_exp2(s[j].z - mn1);
            float pw = fast_exp2(s[j].w - mn1);
            s0 += px + py;
            s1 += pz + pw;
            int cix = j * 8 + lc * 2;
            uint2 u0 = {f2tf32(px), f2tf32(py)};
            uint2 u1 = {f2tf32(pz), f2tf32(pw)};
            *(uint2*)&pp[row0 + cix] = u0;
            *(uint2*)&pp[row1 + cix] = u1;
        }
        s0 += __shfl_xor_sync(0xffffffffu, s0, 1);
        s0 += __shfl_xor_sync(0xffffffffu, s0, 2);
        s1 += __shfl_xor_sync(0xffffffffu, s1, 1);
        s1 += __shfl_xor_sync(0xffffffffu, s1, 2);
        l0 = l0 * a0 + s0;
        l1 = l1 * a1 + s1;
#pragma unroll
        for (int j = 0; j < 8; ++j) {
            o[j].x *= a0; o[j].y *= a0;
            o[j].z *= a1; o[j].w *= a1;
        }
        __syncwarp();   // P rows warp-private

        // O += P V : A-frags via LDSM on P; B-frags via conflict-free scalar LDS
        const unsigned* vsW = (const unsigned*)(Vs + cur * 64 * SV);
#pragma unroll
        for (int kk = 0; kk < 8; ++kk) {
            const int k0 = kk * 8;
            unsigned af[4];
            ldsm4(af[0], af[1], af[2], af[3], pQ + kk * 8 * 4);
#pragma unroll
            for (int j = 0; j < 8; ++j) {
                unsigned b0 = vsW[(k0 + lc)     * SV + j * 8 + lr];
                unsigned b1 = vsW[(k0 + lc + 4) * SV + j * 8 + lr];
                mma_tf32(o[j], af, b0, b1);
            }
        }
        // no trailing syncthreads: next-iter top sync orders K/V buffer reuse
    }

    // Epilogue: normalize, emit tf32 into g_attv
    float inv0 = 1.0f / l0;
    float inv1 = 1.0f / l1;
    const int b = bh >> 4;
    const int h = bh & 15;
    const int t0 = qb * 128 + w16 + lr;
#pragma unroll
    for (int j = 0; j < 8; ++j) {
        int col = h * 64 + j * 8 + lc * 2;
        uint2 r0 = {f2tf32(o[j].x * inv0), f2tf32(o[j].y * inv0)};
        uint2 r1 = {f2tf32(o[j].z * inv1), f2tf32(o[j].w * inv1)};
        *(uint2*)(g_attv + (size_t)(b * T_SEQ + t0) * CDIM + col) = r0;
        *(uint2*)(g_attv + (size_t)(b * T_SEQ + t0 + 8) * CDIM + col) = r1;
    }
}

// ---------------------------------------------------------------------------
extern "C" void kernel_launch(void* const* d_in, const int* in_sizes, int n_in,
                              void* d_out, int out_size)
{
    const float* x    = (const float*)d_in[0];
    const float* Wqkv = (const float*)d_in[1];
    const float* bqkv = (const float*)d_in[2];
    const float* Wout = (const float*)d_in[3];
    const float* bout = (const float*)d_in[4];
    float* out = (float*)d_out;

    cudaFuncSetAttribute(gemm_tc<1>, cudaFuncAttributeMaxDynamicSharedMemorySize, GEMM_SMEM_BYTES);
    cudaFuncSetAttribute(gemm_tc<2>, cudaFuncAttributeMaxDynamicSharedMemorySize, GEMM_SMEM_BYTES);
    cudaFuncSetAttribute(attn_tc_kernel, cudaFuncAttributeMaxDynamicSharedMemorySize, ATT_SMEM_BYTES);

    float* d_xa;   cudaGetSymbolAddress((void**)&d_xa,   g_xa);
    float* d_wq;   cudaGetSymbolAddress((void**)&d_wq,   g_wqkv);
    float* d_wo;   cudaGetSymbolAddress((void**)&d_wo,   g_wout);

    // Pre-convert operands to tf32 (RNA)
    cvt_tf32_kernel<<<592, 256>>>((const float4*)x,    (float4*)d_xa, MROWS * CDIM / 4);
    cvt_tf32_kernel<<<592, 256>>>((const float4*)Wqkv, (float4*)d_wq, 3 * CDIM * CDIM / 4);
    cvt_tf32_kernel<<<592, 256>>>((const float4*)Wout, (float4*)d_wo, CDIM * CDIM / 4);

    // QKV projection: M=8192, N=3072, K=1024 -> scatter tf32 q/k/v
    gemm_tc<1><<<dim3(3072 / 128, MROWS / 128), 256, GEMM_SMEM_BYTES>>>(
        bqkv, nullptr, 3 * CDIM, CDIM);

    // Attention
    attn_tc_kernel<<<dim3(T_SEQ / 128, BATCH * NH), 256, ATT_SMEM_BYTES>>>();

    // Output projection: M=8192, N=1024, K=1024
    gemm_tc<2><<<dim3(CDIM / 128, MROWS / 128), 256, GEMM_SMEM_BYTES>>>(
        bout, out, CDIM, CDIM);
}